// round 15
// baseline (speedup 1.0000x reference)
#include <cuda_runtime.h>
#include <math.h>

#define BB 4
#define LL 4096
#define DD 1024
#define NC 64            // chunks
#define LC (LL / NC)     // 64 steps per chunk
#define LANES (DD / 2)   // 512 float2 lanes
#define TPB 128

// scratch: per (b, chunk, d) complex state. 2 MB. pass2 rewrites in place.
__device__ float2 g_scratch[BB * NC * DD];

__device__ __forceinline__ float2 cmul(float2 a, float2 b) {
    return make_float2(fmaf(a.x, b.x, -a.y * b.y), fmaf(a.x, b.y, a.y * b.x));
}

__device__ __forceinline__ float2 get_phazor(const float* __restrict__ pr,
                                             const float* __restrict__ pi, int d) {
    float r = pr[d], i = pi[d];
    float mag = sqrtf(fmaf(r, r, i * i));
    float s = expf(-mag) / mag;
    return make_float2(r * s, i * s);
}

// step: S = p*S + x  (complex)
__device__ __forceinline__ void cstep(float2& S, const float2 p, const float xv) {
    float nr = fmaf(p.x, S.x, fmaf(-p.y, S.y, xv));
    float ni = fmaf(p.x, S.y, p.y * S.x);
    S.x = nr; S.y = ni;
}

// -------- pass 1: plain LDG double-buffered batch-8 (R7 geometry, 14.98us),
//          NC=64 layout feeding R11's pass2/pass3 unchanged --------
__global__ void __launch_bounds__(TPB) pass1_kernel(const float* __restrict__ x,
                                                    const float* __restrict__ pr,
                                                    const float* __restrict__ pi) {
    int lane = blockIdx.x * TPB + threadIdx.x;  // 0..511
    int c = blockIdx.y;                          // 0..63
    int b = blockIdx.z;
    int d0 = lane * 2;

    float2 p0 = get_phazor(pr, pi, d0);
    float2 p1 = get_phazor(pr, pi, d0 + 1);

    const float2* xp = (const float2*)x + ((size_t)b * LL + (size_t)c * LC) * LANES + lane;

    float2 xs[2][8];
#pragma unroll
    for (int j = 0; j < 8; j++) xs[0][j] = xp[(size_t)j * LANES];

    float2 S0 = make_float2(0.f, 0.f);
    float2 S1 = make_float2(0.f, 0.f);
#pragma unroll
    for (int i = 0; i < LC; i += 8) {
        int cur = (i >> 3) & 1;
        if (i + 8 < LC) {
#pragma unroll
            for (int j = 0; j < 8; j++)
                xs[cur ^ 1][j] = xp[(size_t)(i + 8 + j) * LANES];
        }
#pragma unroll
        for (int j = 0; j < 8; j++) {
            cstep(S0, p0, xs[cur][j].x);
            cstep(S1, p1, xs[cur][j].y);
        }
    }
    ((float4*)g_scratch)[((size_t)b * NC + c) * LANES + lane] =
        make_float4(S0.x, S0.y, S1.x, S1.y);
}

// -------- pass 2 (R11 verbatim): sequential combine across chunks, in place --------
__global__ void __launch_bounds__(256) pass2_kernel(const float* __restrict__ pr,
                                                    const float* __restrict__ pi) {
    int idx = blockIdx.x * blockDim.x + threadIdx.x; // 0..4095
    int d = idx & (DD - 1);
    int b = idx / DD;

    float2 p = get_phazor(pr, pi, d);
    float2 A = p;
#pragma unroll
    for (int k = 0; k < 6; k++) A = cmul(A, A);      // p^64 = p^LC

    float2 S = make_float2(0.f, 0.f);
#pragma unroll 1
    for (int cb = 0; cb < NC; cb += 16) {
        float2 loc[16];
#pragma unroll
        for (int j = 0; j < 16; j++)
            loc[j] = g_scratch[((size_t)b * NC + cb + j) * DD + d];
#pragma unroll
        for (int j = 0; j < 16; j++) {
            g_scratch[((size_t)b * NC + cb + j) * DD + d] = S;  // incoming state
            float nr = fmaf(A.x, S.x, fmaf(-A.y, S.y, loc[j].x));
            float ni = fmaf(A.x, S.y, fmaf(A.y, S.x, loc[j].y));
            S.x = nr; S.y = ni;
        }
    }
}

// -------- pass 3 (R11 verbatim): recompute with true incoming state, write output --------
template <bool CPLX>
__global__ void __launch_bounds__(TPB) pass3_kernel(const float* __restrict__ x,
                                                    const float* __restrict__ hr,
                                                    const float* __restrict__ hi,
                                                    const float* __restrict__ pr,
                                                    const float* __restrict__ pi,
                                                    const float* __restrict__ ir_,
                                                    const float* __restrict__ ii_,
                                                    float* __restrict__ out) {
    int lane = blockIdx.x * TPB + threadIdx.x;  // 0..511
    int c = blockIdx.y;
    int b = blockIdx.z;
    int d0 = lane * 2;

    float2 p0 = get_phazor(pr, pi, d0);
    float2 p1 = get_phazor(pr, pi, d0 + 1);

    // pc = p^(c*LC + 1) via A = p^LC, A^c binary pow (c uniform per block)
    float2 A0 = p0, A1 = p1;
#pragma unroll
    for (int k = 0; k < 6; k++) { A0 = cmul(A0, A0); A1 = cmul(A1, A1); }
    float2 Ae0 = make_float2(1.f, 0.f), Ae1 = make_float2(1.f, 0.f);
    float2 b0 = A0, b1 = A1;
    int e = c;
    while (e) {
        if (e & 1) { Ae0 = cmul(Ae0, b0); Ae1 = cmul(Ae1, b1); }
        b0 = cmul(b0, b0); b1 = cmul(b1, b1);
        e >>= 1;
    }
    float2 pc0 = cmul(p0, Ae0);
    float2 pc1 = cmul(p1, Ae1);

    float2 h0 = make_float2(hr[(size_t)b * DD + d0], hi[(size_t)b * DD + d0]);
    float2 h1 = make_float2(hr[(size_t)b * DD + d0 + 1], hi[(size_t)b * DD + d0 + 1]);
    float2 hp0 = cmul(h0, pc0);   // hidden * p^(t+1) at t = c*LC
    float2 hp1 = cmul(h1, pc1);
    float2 i0 = make_float2(ir_[d0], ii_[d0]);
    float2 i1 = make_float2(ir_[d0 + 1], ii_[d0 + 1]);

    float4 sld = ((const float4*)g_scratch)[((size_t)b * NC + c) * LANES + lane];
    float2 S0 = make_float2(sld.x, sld.y);
    float2 S1 = make_float2(sld.z, sld.w);

    size_t pair0 = ((size_t)b * LL + (size_t)c * LC) * LANES + lane;
    const float2* xp = (const float2*)x + pair0;

    float2 xs[2][8];
#pragma unroll
    for (int j = 0; j < 8; j++) xs[0][j] = __ldcs(xp + (size_t)j * LANES);

#pragma unroll
    for (int i = 0; i < LC; i += 8) {
        int cur = (i >> 3) & 1;
        if (i + 8 < LC) {
#pragma unroll
            for (int j = 0; j < 8; j++)
                xs[cur ^ 1][j] = __ldcs(xp + (size_t)(i + 8 + j) * LANES);
        }
#pragma unroll
        for (int j = 0; j < 8; j++) {
            cstep(S0, p0, xs[cur][j].x);
            cstep(S1, p1, xs[cur][j].y);
            size_t pidx = pair0 + (size_t)(i + j) * LANES;
            if (CPLX) {
                float2 o0, o1;
                o0.x = fmaf(i0.x, S0.x, fmaf(-i0.y, S0.y, hp0.x));
                o0.y = fmaf(i0.x, S0.y, fmaf(i0.y, S0.x, hp0.y));
                o1.x = fmaf(i1.x, S1.x, fmaf(-i1.y, S1.y, hp1.x));
                o1.y = fmaf(i1.x, S1.y, fmaf(i1.y, S1.x, hp1.y));
                __stcs((float4*)out + pidx, make_float4(o0.x, o0.y, o1.x, o1.y));
            } else {
                // real-only output: one vectorized 8B store for (d0, d0+1)
                float r0 = fmaf(i0.x, S0.x, fmaf(-i0.y, S0.y, hp0.x));
                float r1 = fmaf(i1.x, S1.x, fmaf(-i1.y, S1.y, hp1.x));
                __stcs((float2*)out + pidx, make_float2(r0, r1));
            }
            // hp *= p
            float t0r = fmaf(hp0.x, p0.x, -hp0.y * p0.y);
            float t0i = fmaf(hp0.x, p0.y, hp0.y * p0.x);
            hp0.x = t0r; hp0.y = t0i;
            float t1r = fmaf(hp1.x, p1.x, -hp1.y * p1.y);
            float t1i = fmaf(hp1.x, p1.y, hp1.y * p1.x);
            hp1.x = t1r; hp1.y = t1i;
        }
    }
}

extern "C" void kernel_launch(void* const* d_in, const int* in_sizes, int n_in,
                              void* d_out, int out_size) {
    const long long X_SZ = (long long)BB * LL * DD;  // 16,777,216
    const long long H_SZ = (long long)BB * DD;       // 4096
    const long long P_SZ = DD;                       // 1024

    int ix = -1;
    long long scale = 1;
    for (int i = 0; i < n_in; i++)
        if ((long long)in_sizes[i] == X_SZ) { ix = i; scale = 1; break; }
    if (ix < 0)
        for (int i = 0; i < n_in; i++)
            if ((long long)in_sizes[i] == X_SZ * 4) { ix = i; scale = 4; break; }

    const float *x, *hr, *hi, *pr, *pi, *ir_, *ii_;
    bool mapped = false;

    if (ix >= 0 && ix == n_in - 1 && n_in == 7) {
        // Alphabetical ordering
        hi  = (const float*)d_in[0];
        hr  = (const float*)d_in[1];
        pi  = (const float*)d_in[2];
        ii_ = (const float*)d_in[3];
        ir_ = (const float*)d_in[4];
        pr  = (const float*)d_in[5];
        x   = (const float*)d_in[6];
        mapped = true;
    } else if (ix >= 0) {
        x = (const float*)d_in[ix];
        const float* h_list[2] = {0, 0};
        const float* p_list[4] = {0, 0, 0, 0};
        int nh = 0, np = 0;
        for (int i = 0; i < n_in; i++) {
            if (i == ix) continue;
            long long s = (long long)in_sizes[i];
            if (s == H_SZ * scale && nh < 2) h_list[nh++] = (const float*)d_in[i];
            else if (s == P_SZ * scale && np < 4) p_list[np++] = (const float*)d_in[i];
        }
        if (nh == 2 && np == 4) {
            hr  = h_list[0]; hi  = h_list[1];
            pr  = p_list[0]; pi  = p_list[1];
            ir_ = p_list[2]; ii_ = p_list[3];
            mapped = true;
        }
    }
    if (!mapped) {
        x   = (const float*)d_in[0];
        hr  = (const float*)d_in[1];
        hi  = (const float*)d_in[2];
        pr  = (const float*)d_in[3];
        pi  = (const float*)d_in[4];
        ir_ = (const float*)d_in[5];
        ii_ = (const float*)d_in[6];
    }

    long long osz = (long long)out_size;
    bool cplx;
    if (osz == 2 * X_SZ || osz == 8 * X_SZ)       cplx = true;
    else if (osz == X_SZ || osz == 4 * X_SZ)      cplx = false;
    else                                          cplx = true;

    float* out = (float*)d_out;

    dim3 grid1(LANES / TPB, NC, BB);   // (4, 64, 4) = 1024 blocks x 128 threads
    pass1_kernel<<<grid1, TPB>>>(x, pr, pi);
    pass2_kernel<<<(BB * DD) / 256, 256>>>(pr, pi);
    dim3 grid3(LANES / TPB, NC, BB);   // (4, 64, 4) = 1024 blocks x 128 threads
    if (cplx)
        pass3_kernel<true ><<<grid3, TPB>>>(x, hr, hi, pr, pi, ir_, ii_, out);
    else
        pass3_kernel<false><<<grid3, TPB>>>(x, hr, hi, pr, pi, ir_, ii_, out);
}